// round 8
// baseline (speedup 1.0000x reference)
#include <cuda_runtime.h>
#include <cuda_bf16.h>
#include <cstdint>

#define T_LEN 4096
#define DEMB  256
#define HDIM  256
#define NGATE 1024          // 4*HDIM
#define TAGS  32
#define STARTT 30
#define STOPT  31
#define NEGV  (-10000.0f)

// ---------------- scratch (static device globals; no allocation) ----------------
__device__ __align__(16) float g_x[(size_t)T_LEN * DEMB];               // 4 MB
__device__ __align__(16) float g_xg[(size_t)2 * T_LEN * NGATE];         // 32 MB
__device__ __align__(16) float g_hs[(size_t)2 * T_LEN * HDIM];          // 8 MB
__device__ __align__(16) float g_feats[(size_t)T_LEN * TAGS];           // 512 KB
__device__ __align__(16) unsigned g_prog[16];                           // progress flags

// ---------------- small helpers ----------------
__device__ __forceinline__ float sigf(float x)   { return 1.0f / (1.0f + __expf(-x)); }
__device__ __forceinline__ float tanh_f(float x) { return 1.0f - 2.0f / (__expf(2.0f * x) + 1.0f); }

// packed fp32x2 fma: acc = a*b + acc (full fp32, 2 MACs / instruction)
#define FMA2(acc, a, b) \
    asm("fma.rn.f32x2 %0, %1, %2, %3;" : "=l"(acc) : "l"(a), "l"(b), "l"(acc))

// ---------------- phase 1a: embedding gather (+ zero progress flags) ----------------
__global__ __launch_bounds__(256) void k_embed(const int* __restrict__ seq,
                                               const float* __restrict__ E) {
    int t = blockIdx.x;
    int d = threadIdx.x;
    if (blockIdx.x == 0 && threadIdx.x < 16) g_prog[threadIdx.x] = 0u;
    g_x[(size_t)t * DEMB + d] = E[(size_t)seq[t] * DEMB + d];
}

// ---------------- phase 1b: input projections xg = x @ Wih^T + (bih+bhh) ----------------
__global__ __launch_bounds__(256) void k_xg(const float* __restrict__ WihF,
                                            const float* __restrict__ WihB,
                                            const float* __restrict__ bihF,
                                            const float* __restrict__ bhhF,
                                            const float* __restrict__ bihB,
                                            const float* __restrict__ bhhB) {
    const int BM = 64, BN = 64, BK = 16, PAD = 4;
    __shared__ __align__(16) float sA[BK][BM + PAD];
    __shared__ __align__(16) float sB[BK][BN + PAD];

    const int dir = blockIdx.z;
    const float* __restrict__ W  = dir ? WihB : WihF;
    const float* __restrict__ b1 = dir ? bihB : bihF;
    const float* __restrict__ b2 = dir ? bhhB : bhhF;

    const int n0 = blockIdx.x * BN;
    const int t0 = blockIdx.y * BM;
    const int tid = threadIdx.x;
    const int tx = tid & 15, ty = tid >> 4;
    const int lm = tid >> 2, lq = tid & 3;

    float acc[4][4];
#pragma unroll
    for (int i = 0; i < 4; i++)
#pragma unroll
        for (int j = 0; j < 4; j++) acc[i][j] = 0.0f;

    for (int k0 = 0; k0 < DEMB; k0 += BK) {
        float4 av = *reinterpret_cast<const float4*>(&g_x[(size_t)(t0 + lm) * DEMB + k0 + lq * 4]);
        float4 bv = *reinterpret_cast<const float4*>(&W[(size_t)(n0 + lm) * DEMB + k0 + lq * 4]);
        sA[lq * 4 + 0][lm] = av.x; sA[lq * 4 + 1][lm] = av.y;
        sA[lq * 4 + 2][lm] = av.z; sA[lq * 4 + 3][lm] = av.w;
        sB[lq * 4 + 0][lm] = bv.x; sB[lq * 4 + 1][lm] = bv.y;
        sB[lq * 4 + 2][lm] = bv.z; sB[lq * 4 + 3][lm] = bv.w;
        __syncthreads();
#pragma unroll
        for (int kk = 0; kk < BK; kk++) {
            float4 a4 = *reinterpret_cast<const float4*>(&sA[kk][ty * 4]);
            float4 b4 = *reinterpret_cast<const float4*>(&sB[kk][tx * 4]);
            float a[4] = {a4.x, a4.y, a4.z, a4.w};
            float b[4] = {b4.x, b4.y, b4.z, b4.w};
#pragma unroll
            for (int i = 0; i < 4; i++)
#pragma unroll
                for (int j = 0; j < 4; j++) acc[i][j] += a[i] * b[j];
        }
        __syncthreads();
    }
#pragma unroll
    for (int i = 0; i < 4; i++) {
        int row = t0 + ty * 4 + i;
#pragma unroll
        for (int j = 0; j < 4; j++) {
            int col = n0 + tx * 4 + j;
            g_xg[((size_t)dir * T_LEN + row) * NGATE + col] = acc[i][j] + b1[col] + b2[col];
        }
    }
}

// ---------------- phase 2: recurrence v5 — NO clusters, L2-mediated exchange --------------
// 16 independent CTAs (8 per dir) x 256 threads; CTA owns 32 hidden units.
// Dot engine as R5 (f32x2, interleaved chunks, butterfly shfl). h rows live in g_hs
// (append-only: fresh address per step -> no overwrite hazards). Sync: monotonic global
// flags g_prog[dir*8+rank] = steps completed; canonical STG -> __syncthreads ->
// __threadfence -> flag pattern; consumers poll with ld.volatile + __threadfence on exit.
// seen_min caching skips poll+fence when an earlier poll already proved prog >= s.
__global__ __launch_bounds__(256, 1)
void k_rec(const float* __restrict__ WhhF, const float* __restrict__ WhhB,
           const float* __restrict__ h0,   const float* __restrict__ c0) {
    const int cta  = blockIdx.x;
    const int dir  = cta >> 3;
    const int rank = cta & 7;
    const int tid  = threadIdx.x;
    const int unit_local = tid >> 3;              // 0..31
    const int chunk      = tid & 7;               // 0..7
    const int unit       = rank * 32 + unit_local;
    const bool producer  = (chunk == 0);

    const float* __restrict__ Whh = dir ? WhhB : WhhF;

    // ---- register-resident weights: 4 gates x 8 interleaved float4s (as f32x2 pairs) ----
    unsigned long long w[4][16];
#pragma unroll
    for (int g = 0; g < 4; g++) {
        const float* wrow = Whh + ((size_t)g * HDIM + unit) * HDIM;
#pragma unroll
        for (int j = 0; j < 8; j++) {
            ulonglong2 v = *reinterpret_cast<const ulonglong2*>(wrow + j * 32 + chunk * 4);
            w[g][2 * j]     = v.x;
            w[g][2 * j + 1] = v.y;
        }
    }

    float c = producer ? c0[dir * HDIM + unit] : 0.0f;

    // xg pointer + initial prefetch (producers only)
    const float* __restrict__ xgp = g_xg + (size_t)dir * T_LEN * NGATE + unit;
    float xgc[4];
    if (producer) {
        const int t0 = dir ? (T_LEN - 1) : 0;
#pragma unroll
        for (int g = 0; g < 4; g++) xgc[g] = __ldg(xgp + (size_t)t0 * NGATE + g * HDIM);
    }

    const float* __restrict__ hs_base = g_hs + (size_t)dir * T_LEN * HDIM;
    float* __restrict__ hs_out = g_hs + (size_t)dir * T_LEN * HDIM;
    unsigned* const prog = &g_prog[dir * 8];

    unsigned seen_min = 0;   // proven lower bound on min_r prog[r]

    for (int s = 0; s < T_LEN; s++) {
        const int t = dir ? (T_LEN - 1 - s) : s;

        // source row of h_{s-1}
        const float* hrow = (s == 0) ? (h0 + dir * HDIM)
                                     : (hs_base + (size_t)(dir ? (t + 1) : (t - 1)) * HDIM);

        if (s && seen_min < (unsigned)s) {
            unsigned mn;
            do {
                unsigned f0, f1, f2, f3, f4, f5, f6, f7;
                asm volatile("ld.volatile.global.v4.u32 {%0,%1,%2,%3}, [%4];"
                             : "=r"(f0), "=r"(f1), "=r"(f2), "=r"(f3) : "l"(prog));
                asm volatile("ld.volatile.global.v4.u32 {%0,%1,%2,%3}, [%4];"
                             : "=r"(f4), "=r"(f5), "=r"(f6), "=r"(f7) : "l"(prog + 4));
                mn = min(min(min(f0, f1), min(f2, f3)), min(min(f4, f5), min(f6, f7)));
            } while (mn < (unsigned)s);
            seen_min = mn;
            __threadfence();   // acquire side: h rows up to seen_min now visible
        }

        // ---- load h (8 x LDG.128, broadcast-coalesced across the warp) + dot ----
        unsigned long long acc[4] = {0ull, 0ull, 0ull, 0ull};
#pragma unroll
        for (int j = 0; j < 8; j++) {
            ulonglong2 hv = *reinterpret_cast<const ulonglong2*>(hrow + j * 32 + chunk * 4);
#pragma unroll
            for (int g = 0; g < 4; g++) {
                FMA2(acc[g], w[g][2 * j],     hv.x);
                FMA2(acc[g], w[g][2 * j + 1], hv.y);
            }
        }

        float gs[4];
#pragma unroll
        for (int g = 0; g < 4; g++) {
            float lo, hi;
            asm("mov.b64 {%0,%1}, %2;" : "=f"(lo), "=f"(hi) : "l"(acc[g]));
            gs[g] = lo + hi;
        }
        // butterfly over chunk bits (lane bits 0..2)
#pragma unroll
        for (int m = 1; m < 8; m <<= 1) {
#pragma unroll
            for (int g = 0; g < 4; g++)
                gs[g] += __shfl_xor_sync(0xffffffffu, gs[g], m);
        }

        if (producer) {
            float gi = gs[0] + xgc[0];
            float gf = gs[1] + xgc[1];
            float gg = gs[2] + xgc[2];
            float go = gs[3] + xgc[3];
            if (s + 1 < T_LEN) {                    // prefetch next xg behind MUFUs
                const int tn = dir ? (T_LEN - 2 - s) : (s + 1);
#pragma unroll
                for (int g = 0; g < 4; g++) xgc[g] = __ldg(xgp + (size_t)tn * NGATE + g * HDIM);
            }
            float ii = sigf(gi), ff = sigf(gf), tg = tanh_f(gg), oo = sigf(go);
            c = ff * c + ii * tg;
            float h = oo * tanh_f(c);
            hs_out[(size_t)t * HDIM + unit] = h;    // fresh row: the exchange medium
        }
        __syncthreads();                            // all 32 unit stores of this CTA done
        if (tid == 0) {
            __threadfence();                        // release: h row visible before flag
            asm volatile("st.volatile.global.u32 [%0], %1;"
                         :: "l"(prog + rank), "r"((unsigned)(s + 1)));
        }
    }
}

// ---------------- phase 3: feats[t,k] = [hf(t);hb(t)] . W_out[k] + b_out[k] ----------------
__global__ __launch_bounds__(256) void k_feats(const float* __restrict__ Wout,
                                               const float* __restrict__ bout) {
    const int k  = threadIdx.x & 31;
    const int tl = threadIdx.x >> 5;
    const int t  = blockIdx.x * 8 + tl;
    const float4* hf = reinterpret_cast<const float4*>(g_hs + (size_t)t * HDIM);
    const float4* hb = reinterpret_cast<const float4*>(g_hs + (size_t)T_LEN * HDIM + (size_t)t * HDIM);
    const float4* wr = reinterpret_cast<const float4*>(Wout + (size_t)k * 512);
    float acc = bout[k];
#pragma unroll 8
    for (int d = 0; d < 64; d++) {
        float4 h4 = hf[d]; float4 w4 = wr[d];
        acc += h4.x * w4.x + h4.y * w4.y + h4.z * w4.z + h4.w * w4.w;
    }
#pragma unroll 8
    for (int d = 0; d < 64; d++) {
        float4 h4 = hb[d]; float4 w4 = wr[64 + d];
        acc += h4.x * w4.x + h4.y * w4.y + h4.z * w4.z + h4.w * w4.w;
    }
    g_feats[(size_t)t * TAGS + k] = acc;
}

// ---------------- phase 4: Viterbi forward + backtrace (1 warp; bps in dyn smem) -----------
__global__ void k_viterbi(const float* __restrict__ trans, float* __restrict__ out,
                          int out_size) {
    extern __shared__ unsigned char bps[];
    const int lane = threadIdx.x;

    float tr[TAGS];
#pragma unroll
    for (int p = 0; p < TAGS; p++) tr[p] = trans[lane * TAGS + p];
    const float trs = trans[STOPT * TAGS + lane];

    float fv = (lane == STARTT) ? 0.0f : NEGV;
    float fnext = g_feats[lane];
    for (int t = 0; t < T_LEN; t++) {
        const float feat = fnext;
        if (t + 1 < T_LEN) fnext = g_feats[(size_t)(t + 1) * TAGS + lane];
        float best = -3.4e38f; int bi = 0;
#pragma unroll
        for (int p = 0; p < TAGS; p++) {
            float s = __shfl_sync(0xffffffffu, fv, p) + tr[p];
            if (s > best) { best = s; bi = p; }
        }
        fv = best + feat;
        bps[(size_t)t * TAGS + lane] = (unsigned char)bi;
    }
    __syncwarp();

    float bv = fv + trs; int bidx = lane;
#pragma unroll
    for (int off = 16; off; off >>= 1) {
        float ov = __shfl_down_sync(0xffffffffu, bv, off);
        int   oi = __shfl_down_sync(0xffffffffu, bidx, off);
        if (ov > bv || (ov == bv && oi < bidx)) { bv = ov; bidx = oi; }
    }
    if (lane == 0) {
        const int off = (out_size > T_LEN) ? 1 : 0;
        if (off) out[0] = bv;
        int b = bidx;
        out[off + T_LEN - 1] = (float)b;
        for (int t = T_LEN - 1; t >= 1; --t) {
            b = (int)bps[(size_t)t * TAGS + b];
            out[off + t - 1] = (float)b;
        }
    }
}

// ---------------- launch ----------------
extern "C" void kernel_launch(void* const* d_in, const int* in_sizes, int n_in,
                              void* d_out, int out_size) {
    (void)in_sizes; (void)n_in;
    const int*   seq   = (const int*)  d_in[0];
    const float* E     = (const float*)d_in[1];
    const float* WihF  = (const float*)d_in[2];
    const float* WhhF  = (const float*)d_in[3];
    const float* bihF  = (const float*)d_in[4];
    const float* bhhF  = (const float*)d_in[5];
    const float* WihB  = (const float*)d_in[6];
    const float* WhhB  = (const float*)d_in[7];
    const float* bihB  = (const float*)d_in[8];
    const float* bhhB  = (const float*)d_in[9];
    const float* h0    = (const float*)d_in[10];
    const float* c0    = (const float*)d_in[11];
    const float* Wout  = (const float*)d_in[12];
    const float* bout  = (const float*)d_in[13];
    const float* trans = (const float*)d_in[14];
    float* out = (float*)d_out;

    k_embed<<<T_LEN, 256>>>(seq, E);
    dim3 gg(NGATE / 64, T_LEN / 64, 2);
    k_xg<<<gg, 256>>>(WihF, WihB, bihF, bhhF, bihB, bhhB);
    k_rec<<<16, 256>>>(WhhF, WhhB, h0, c0);
    k_feats<<<T_LEN / 8, 256>>>(Wout, bout);
    cudaFuncSetAttribute(k_viterbi, cudaFuncAttributeMaxDynamicSharedMemorySize,
                         T_LEN * TAGS);
    k_viterbi<<<1, 32, T_LEN * TAGS>>>(trans, out, out_size);
}

// round 9
// speedup vs baseline: 2.7212x; 2.7212x over previous
#include <cuda_runtime.h>
#include <cuda_bf16.h>
#include <cstdint>

#define T_LEN 4096
#define DEMB  256
#define HDIM  256
#define NGATE 1024          // 4*HDIM
#define TAGS  32
#define STARTT 30
#define STOPT  31
#define NEGV  (-10000.0f)

// ---------------- scratch (static device globals; no allocation) ----------------
__device__ __align__(16) float g_x[(size_t)T_LEN * DEMB];               // 4 MB
__device__ __align__(16) float g_xg[(size_t)2 * T_LEN * NGATE];         // 32 MB
__device__ __align__(16) float g_hs[(size_t)2 * T_LEN * HDIM];          // 8 MB
__device__ __align__(16) float g_feats[(size_t)T_LEN * TAGS];           // 512 KB

// ---------------- small helpers ----------------
__device__ __forceinline__ float sigf(float x)   { return 1.0f / (1.0f + __expf(-x)); }
__device__ __forceinline__ float tanh_f(float x) { return 1.0f - 2.0f / (__expf(2.0f * x) + 1.0f); }

__device__ __forceinline__ unsigned cluster_rank() {
    unsigned r; asm("mov.u32 %0, %%cluster_ctarank;" : "=r"(r)); return r;
}
__device__ __forceinline__ void cluster_sync_() {
    asm volatile("barrier.cluster.arrive.aligned;\n\tbarrier.cluster.wait.aligned;" ::: "memory");
}
__device__ __forceinline__ void cluster_arrive_() {
    asm volatile("barrier.cluster.arrive.aligned;" ::: "memory");   // release
}
__device__ __forceinline__ void cluster_wait_() {
    asm volatile("barrier.cluster.wait.aligned;" ::: "memory");     // acquire
}
__device__ __forceinline__ uint32_t smem_u32(const void* p) {
    return (uint32_t)__cvta_generic_to_shared(const_cast<void*>(p));
}
__device__ __forceinline__ uint32_t mapa_u32(uint32_t saddr, int r) {
    uint32_t d;
    asm("mapa.shared::cluster.u32 %0, %1, %2;" : "=r"(d) : "r"(saddr), "r"(r));
    return d;
}

// packed fp32x2 fma: acc = a*b + acc (full fp32, 2 MACs / instruction)
#define FMA2(acc, a, b) \
    asm("fma.rn.f32x2 %0, %1, %2, %3;" : "=l"(acc) : "l"(a), "l"(b), "l"(acc))

// ---------------- phase 1a: embedding gather ----------------
__global__ __launch_bounds__(256) void k_embed(const int* __restrict__ seq,
                                               const float* __restrict__ E) {
    int t = blockIdx.x;
    int d = threadIdx.x;
    g_x[(size_t)t * DEMB + d] = E[(size_t)seq[t] * DEMB + d];
}

// ---------------- phase 1b: input projections xg = x @ Wih^T + (bih+bhh) ----------------
__global__ __launch_bounds__(256) void k_xg(const float* __restrict__ WihF,
                                            const float* __restrict__ WihB,
                                            const float* __restrict__ bihF,
                                            const float* __restrict__ bhhF,
                                            const float* __restrict__ bihB,
                                            const float* __restrict__ bhhB) {
    const int BM = 64, BN = 64, BK = 16, PAD = 4;
    __shared__ __align__(16) float sA[BK][BM + PAD];
    __shared__ __align__(16) float sB[BK][BN + PAD];

    const int dir = blockIdx.z;
    const float* __restrict__ W  = dir ? WihB : WihF;
    const float* __restrict__ b1 = dir ? bihB : bihF;
    const float* __restrict__ b2 = dir ? bhhB : bhhF;

    const int n0 = blockIdx.x * BN;
    const int t0 = blockIdx.y * BM;
    const int tid = threadIdx.x;
    const int tx = tid & 15, ty = tid >> 4;
    const int lm = tid >> 2, lq = tid & 3;

    float acc[4][4];
#pragma unroll
    for (int i = 0; i < 4; i++)
#pragma unroll
        for (int j = 0; j < 4; j++) acc[i][j] = 0.0f;

    for (int k0 = 0; k0 < DEMB; k0 += BK) {
        float4 av = *reinterpret_cast<const float4*>(&g_x[(size_t)(t0 + lm) * DEMB + k0 + lq * 4]);
        float4 bv = *reinterpret_cast<const float4*>(&W[(size_t)(n0 + lm) * DEMB + k0 + lq * 4]);
        sA[lq * 4 + 0][lm] = av.x; sA[lq * 4 + 1][lm] = av.y;
        sA[lq * 4 + 2][lm] = av.z; sA[lq * 4 + 3][lm] = av.w;
        sB[lq * 4 + 0][lm] = bv.x; sB[lq * 4 + 1][lm] = bv.y;
        sB[lq * 4 + 2][lm] = bv.z; sB[lq * 4 + 3][lm] = bv.w;
        __syncthreads();
#pragma unroll
        for (int kk = 0; kk < BK; kk++) {
            float4 a4 = *reinterpret_cast<const float4*>(&sA[kk][ty * 4]);
            float4 b4 = *reinterpret_cast<const float4*>(&sB[kk][tx * 4]);
            float a[4] = {a4.x, a4.y, a4.z, a4.w};
            float b[4] = {b4.x, b4.y, b4.z, b4.w};
#pragma unroll
            for (int i = 0; i < 4; i++)
#pragma unroll
                for (int j = 0; j < 4; j++) acc[i][j] += a[i] * b[j];
        }
        __syncthreads();
    }
#pragma unroll
    for (int i = 0; i < 4; i++) {
        int row = t0 + ty * 4 + i;
#pragma unroll
        for (int j = 0; j < 4; j++) {
            int col = n0 + tx * 4 + j;
            g_xg[((size_t)dir * T_LEN + row) * NGATE + col] = acc[i][j] + b1[col] + b2[col];
        }
    }
}

// ---------------- phase 2: recurrence v6 --------------------------------------------------
// R5 skeleton (passing): 2 clusters x 8 CTAs x 256 thr, split barrier.cluster per step,
// double-buffered h in smem, f32x2 dot with interleaved conflict-free chunks + butterfly.
// v6 deltas: (a) ALL 8 lanes of a unit-group run the activation redundantly (bit-identical;
// masked lanes burned those slots anyway) so the 8-CTA h broadcast is ONE st.shared::cluster
// across lanes instead of 8 serial stores in one lane; (b) hs_out STG + xg prefetch moved
// AFTER cluster.arrive (off the barrier critical path).
__global__ __launch_bounds__(256, 1) __cluster_dims__(8, 1, 1)
void k_rec(const float* __restrict__ WhhF, const float* __restrict__ WhhB,
           const float* __restrict__ h0,   const float* __restrict__ c0) {
    __shared__ __align__(16) float h_sh[2][HDIM];

    const int rank = (int)cluster_rank();
    const int dir  = (int)(blockIdx.x >> 3);
    const int tid  = threadIdx.x;
    const int unit_local = tid >> 3;              // 0..31
    const int chunk      = tid & 7;               // 0..7
    const int unit       = rank * 32 + unit_local;

    const float* __restrict__ Whh = dir ? WhhB : WhhF;

    // ---- register-resident weights: 4 gates x 8 interleaved float4s (as f32x2 pairs) ----
    unsigned long long w[4][16];
#pragma unroll
    for (int g = 0; g < 4; g++) {
        const float* wrow = Whh + ((size_t)g * HDIM + unit) * HDIM;
#pragma unroll
        for (int j = 0; j < 8; j++) {
            ulonglong2 v = *reinterpret_cast<const ulonglong2*>(wrow + j * 32 + chunk * 4);
            w[g][2 * j]     = v.x;
            w[g][2 * j + 1] = v.y;
        }
    }

    h_sh[0][tid] = h0[dir * HDIM + tid];
    h_sh[1][tid] = 0.0f;
    float c = c0[dir * HDIM + unit];              // replicated across the 8 lanes of a group
    __syncthreads();
    cluster_sync_();   // peers' h_sh init complete before any remote store can land

    // each lane pushes its group's h to CTA == its chunk (one remote store per lane)
    const uint32_t h_rem = mapa_u32(smem_u32(&h_sh[0][0]), chunk);

    // xg pointer + initial prefetch (all lanes of a group load same addrs -> broadcast)
    const float* __restrict__ xgp = g_xg + (size_t)dir * T_LEN * NGATE + unit;
    float xgc[4];
    {
        const int t0 = dir ? (T_LEN - 1) : 0;
#pragma unroll
        for (int g = 0; g < 4; g++) xgc[g] = __ldg(xgp + (size_t)t0 * NGATE + g * HDIM);
    }

    float* __restrict__ hs_out = g_hs + (size_t)dir * T_LEN * HDIM + unit;

    for (int s = 0; s < T_LEN; s++) {
        const int t = dir ? (T_LEN - 1 - s) : s;
        const int b = s & 1;

        if (s) cluster_wait_();   // acquire: step-s h buffer complete cluster-wide

        // ---- dot: 4 gate rows over interleaved 32-elem subset, h loads reused 4x ----
        const float* hb = &h_sh[b][chunk * 4];
        unsigned long long acc[4] = {0ull, 0ull, 0ull, 0ull};
#pragma unroll
        for (int j = 0; j < 8; j++) {
            ulonglong2 hv = *reinterpret_cast<const ulonglong2*>(hb + j * 32);
#pragma unroll
            for (int g = 0; g < 4; g++) {
                FMA2(acc[g], w[g][2 * j],     hv.x);
                FMA2(acc[g], w[g][2 * j + 1], hv.y);
            }
        }

        float gs[4];
#pragma unroll
        for (int g = 0; g < 4; g++) {
            float lo, hi;
            asm("mov.b64 {%0,%1}, %2;" : "=f"(lo), "=f"(hi) : "l"(acc[g]));
            gs[g] = lo + hi;
        }
        // butterfly over chunk bits: all 8 lanes of a group get bit-identical sums
#pragma unroll
        for (int m = 1; m < 8; m <<= 1) {
#pragma unroll
            for (int g = 0; g < 4; g++)
                gs[g] += __shfl_xor_sync(0xffffffffu, gs[g], m);
        }

        // ---- activation: redundant in all 8 lanes (identical arithmetic) ----
        float gi = gs[0] + xgc[0];
        float gf = gs[1] + xgc[1];
        float gg = gs[2] + xgc[2];
        float go = gs[3] + xgc[3];
        float ii = sigf(gi), ff = sigf(gf), tg = tanh_f(gg), oo = sigf(go);
        c = ff * c + ii * tg;
        float h = oo * tanh_f(c);

        if (s + 1 < T_LEN) {
            // ONE instruction: each lane stores h into buf b^1 of CTA 'chunk'
            const uint32_t off = (uint32_t)(((b ^ 1) * HDIM + unit) * 4);
            asm volatile("st.shared::cluster.f32 [%0], %1;"
                         :: "r"(h_rem + off), "f"(h) : "memory");
        }
        cluster_arrive_();   // release: reads of buf b done + stores to buf b^1 issued

        // off the barrier path: persist h, prefetch next xg
        if (chunk == 0) hs_out[(size_t)t * HDIM] = h;
        if (s + 1 < T_LEN) {
            const int tn = dir ? (T_LEN - 2 - s) : (s + 1);
#pragma unroll
            for (int g = 0; g < 4; g++) xgc[g] = __ldg(xgp + (size_t)tn * NGATE + g * HDIM);
        }
    }
    cluster_wait_();         // drain final phase; no CTA exits with peer stores in flight
}

// ---------------- phase 3: feats[t,k] = [hf(t);hb(t)] . W_out[k] + b_out[k] ----------------
__global__ __launch_bounds__(256) void k_feats(const float* __restrict__ Wout,
                                               const float* __restrict__ bout) {
    const int k  = threadIdx.x & 31;
    const int tl = threadIdx.x >> 5;
    const int t  = blockIdx.x * 8 + tl;
    const float4* hf = reinterpret_cast<const float4*>(g_hs + (size_t)t * HDIM);
    const float4* hb = reinterpret_cast<const float4*>(g_hs + (size_t)T_LEN * HDIM + (size_t)t * HDIM);
    const float4* wr = reinterpret_cast<const float4*>(Wout + (size_t)k * 512);
    float acc = bout[k];
#pragma unroll 8
    for (int d = 0; d < 64; d++) {
        float4 h4 = hf[d]; float4 w4 = wr[d];
        acc += h4.x * w4.x + h4.y * w4.y + h4.z * w4.z + h4.w * w4.w;
    }
#pragma unroll 8
    for (int d = 0; d < 64; d++) {
        float4 h4 = hb[d]; float4 w4 = wr[64 + d];
        acc += h4.x * w4.x + h4.y * w4.y + h4.z * w4.z + h4.w * w4.w;
    }
    g_feats[(size_t)t * TAGS + k] = acc;
}

// ---------------- phase 4: Viterbi v2 — tree-max (1 warp; bps in dyn smem) ----------------
// lane = next tag. Per step: 32 independent SHFL+FADD produce all candidate scores, then a
// 5-level left-biased max tree (strict > keeps FIRST max index = jnp.argmax tie rule).
// Dependent chain ~85 cyc vs ~544 for the old 32-long select chain.
__global__ void k_viterbi(const float* __restrict__ trans, float* __restrict__ out,
                          int out_size) {
    extern __shared__ unsigned char bps[];
    const int lane = threadIdx.x;

    float tr[TAGS];
#pragma unroll
    for (int p = 0; p < TAGS; p++) tr[p] = trans[lane * TAGS + p];
    const float trs = trans[STOPT * TAGS + lane];

    float fv = (lane == STARTT) ? 0.0f : NEGV;
    float fnext = g_feats[lane];
    for (int t = 0; t < T_LEN; t++) {
        const float feat = fnext;
        if (t + 1 < T_LEN) fnext = g_feats[(size_t)(t + 1) * TAGS + lane];

        float sc[TAGS];
#pragma unroll
        for (int p = 0; p < TAGS; p++)
            sc[p] = __shfl_sync(0xffffffffu, fv, p) + tr[p];

        // level 1: 16 (value, index) pairs; then 4 more halving levels
        float mv[16]; int mi[16];
#pragma unroll
        for (int i = 0; i < 16; i++) {
            bool take = sc[i + 16] > sc[i];
            mv[i] = take ? sc[i + 16] : sc[i];
            mi[i] = take ? (i + 16) : i;
        }
#pragma unroll
        for (int half = 8; half >= 1; half >>= 1) {
#pragma unroll
            for (int i = 0; i < half; i++) {
                bool take = mv[i + half] > mv[i];
                mv[i] = take ? mv[i + half] : mv[i];
                mi[i] = take ? mi[i + half] : mi[i];
            }
        }
        fv = mv[0] + feat;
        bps[(size_t)t * TAGS + lane] = (unsigned char)mi[0];
    }
    __syncwarp();

    float bv = fv + trs; int bidx = lane;
#pragma unroll
    for (int off = 16; off; off >>= 1) {
        float ov = __shfl_down_sync(0xffffffffu, bv, off);
        int   oi = __shfl_down_sync(0xffffffffu, bidx, off);
        if (ov > bv || (ov == bv && oi < bidx)) { bv = ov; bidx = oi; }
    }
    if (lane == 0) {
        const int off = (out_size > T_LEN) ? 1 : 0;
        if (off) out[0] = bv;
        int b = bidx;
        out[off + T_LEN - 1] = (float)b;
        for (int t = T_LEN - 1; t >= 1; --t) {
            b = (int)bps[(size_t)t * TAGS + b];
            out[off + t - 1] = (float)b;
        }
    }
}

// ---------------- launch ----------------
extern "C" void kernel_launch(void* const* d_in, const int* in_sizes, int n_in,
                              void* d_out, int out_size) {
    (void)in_sizes; (void)n_in;
    const int*   seq   = (const int*)  d_in[0];
    const float* E     = (const float*)d_in[1];
    const float* WihF  = (const float*)d_in[2];
    const float* WhhF  = (const float*)d_in[3];
    const float* bihF  = (const float*)d_in[4];
    const float* bhhF  = (const float*)d_in[5];
    const float* WihB  = (const float*)d_in[6];
    const float* WhhB  = (const float*)d_in[7];
    const float* bihB  = (const float*)d_in[8];
    const float* bhhB  = (const float*)d_in[9];
    const float* h0    = (const float*)d_in[10];
    const float* c0    = (const float*)d_in[11];
    const float* Wout  = (const float*)d_in[12];
    const float* bout  = (const float*)d_in[13];
    const float* trans = (const float*)d_in[14];
    float* out = (float*)d_out;

    k_embed<<<T_LEN, 256>>>(seq, E);
    dim3 gg(NGATE / 64, T_LEN / 64, 2);
    k_xg<<<gg, 256>>>(WihF, WihB, bihF, bhhF, bihB, bhhB);
    k_rec<<<16, 256>>>(WhhF, WhhB, h0, c0);
    k_feats<<<T_LEN / 8, 256>>>(Wout, bout);
    cudaFuncSetAttribute(k_viterbi, cudaFuncAttributeMaxDynamicSharedMemorySize,
                         T_LEN * TAGS);
    k_viterbi<<<1, 32, T_LEN * TAGS>>>(trans, out, out_size);
}

// round 10
// speedup vs baseline: 2.8479x; 1.0466x over previous
#include <cuda_runtime.h>
#include <cuda_bf16.h>
#include <cstdint>

#define T_LEN 4096
#define DEMB  256
#define HDIM  256
#define NGATE 1024          // 4*HDIM
#define TAGS  32
#define STARTT 30
#define STOPT  31
#define NEGV  (-10000.0f)

// ---------------- scratch (static device globals; no allocation) ----------------
__device__ __align__(16) float g_x[(size_t)T_LEN * DEMB];               // 4 MB
__device__ __align__(16) float g_xg[(size_t)2 * T_LEN * NGATE];         // 32 MB
__device__ __align__(16) float g_hs[(size_t)2 * T_LEN * HDIM];          // 8 MB
__device__ __align__(16) float g_feats[(size_t)T_LEN * TAGS];           // 512 KB

// ---------------- small helpers ----------------
__device__ __forceinline__ float sigf(float x)   { return 1.0f / (1.0f + __expf(-x)); }
__device__ __forceinline__ float tanh_f(float x) { return 1.0f - 2.0f / (__expf(2.0f * x) + 1.0f); }

__device__ __forceinline__ unsigned cluster_rank() {
    unsigned r; asm("mov.u32 %0, %%cluster_ctarank;" : "=r"(r)); return r;
}
__device__ __forceinline__ void cluster_sync_() {
    asm volatile("barrier.cluster.arrive.aligned;\n\tbarrier.cluster.wait.aligned;" ::: "memory");
}
__device__ __forceinline__ uint32_t smem_u32(const void* p) {
    return (uint32_t)__cvta_generic_to_shared(const_cast<void*>(p));
}
__device__ __forceinline__ uint32_t mapa_u32(uint32_t saddr, int r) {
    uint32_t d;
    asm("mapa.shared::cluster.u32 %0, %1, %2;" : "=r"(d) : "r"(saddr), "r"(r));
    return d;
}

// canonical mbarrier ops (forms from ptx_helpers.cuh)
#define MBAR_INIT(addr, cnt) \
    asm volatile("mbarrier.init.shared.b64 [%0], %1;" :: "r"(addr), "r"(cnt) : "memory")
#define MBAR_ARRIVE_REMOTE(remote_addr) \
    asm volatile("mbarrier.arrive.shared::cluster.b64 _, [%0];" :: "r"(remote_addr) : "memory")
#define MBAR_WAIT_PARITY(mbar, parity) do {                                             \
    uint32_t _m = (mbar); uint32_t _p = (parity); uint32_t _done;                       \
    asm volatile("{\n\t.reg .pred p;\n\t"                                               \
                 "mbarrier.try_wait.parity.acquire.cta.shared::cta.b64 p, [%1], %2;\n\t"\
                 "selp.b32 %0, 1, 0, p;\n\t}"                                           \
                 : "=r"(_done) : "r"(_m), "r"(_p) : "memory");                          \
    if (!_done) {                                                                       \
        asm volatile("{\n\t.reg .pred P1;\n\t"                                          \
            "W_%=:\n\t"                                                                 \
            "mbarrier.try_wait.parity.acquire.cta.shared::cta.b64 P1, [%0], %1, 0x989680;\n\t" \
            "@P1 bra.uni D_%=;\n\t"                                                     \
            "bra.uni W_%=;\n\t"                                                         \
            "D_%=:\n\t}" :: "r"(_m), "r"(_p) : "memory");                               \
    }                                                                                    \
} while (0)

// packed fp32x2 fma: acc = a*b + acc (full fp32, 2 MACs / instruction)
#define FMA2(acc, a, b) \
    asm("fma.rn.f32x2 %0, %1, %2, %3;" : "=l"(acc) : "l"(a), "l"(b), "l"(acc))

// ---------------- phase 1a: embedding gather ----------------
__global__ __launch_bounds__(256) void k_embed(const int* __restrict__ seq,
                                               const float* __restrict__ E) {
    int t = blockIdx.x;
    int d = threadIdx.x;
    g_x[(size_t)t * DEMB + d] = E[(size_t)seq[t] * DEMB + d];
}

// ---------------- phase 1b: input projections xg = x @ Wih^T + (bih+bhh) ----------------
__global__ __launch_bounds__(256) void k_xg(const float* __restrict__ WihF,
                                            const float* __restrict__ WihB,
                                            const float* __restrict__ bihF,
                                            const float* __restrict__ bhhF,
                                            const float* __restrict__ bihB,
                                            const float* __restrict__ bhhB) {
    const int BM = 64, BN = 64, BK = 16, PAD = 4;
    __shared__ __align__(16) float sA[BK][BM + PAD];
    __shared__ __align__(16) float sB[BK][BN + PAD];

    const int dir = blockIdx.z;
    const float* __restrict__ W  = dir ? WihB : WihF;
    const float* __restrict__ b1 = dir ? bihB : bihF;
    const float* __restrict__ b2 = dir ? bhhB : bhhF;

    const int n0 = blockIdx.x * BN;
    const int t0 = blockIdx.y * BM;
    const int tid = threadIdx.x;
    const int tx = tid & 15, ty = tid >> 4;
    const int lm = tid >> 2, lq = tid & 3;

    float acc[4][4];
#pragma unroll
    for (int i = 0; i < 4; i++)
#pragma unroll
        for (int j = 0; j < 4; j++) acc[i][j] = 0.0f;

    for (int k0 = 0; k0 < DEMB; k0 += BK) {
        float4 av = *reinterpret_cast<const float4*>(&g_x[(size_t)(t0 + lm) * DEMB + k0 + lq * 4]);
        float4 bv = *reinterpret_cast<const float4*>(&W[(size_t)(n0 + lm) * DEMB + k0 + lq * 4]);
        sA[lq * 4 + 0][lm] = av.x; sA[lq * 4 + 1][lm] = av.y;
        sA[lq * 4 + 2][lm] = av.z; sA[lq * 4 + 3][lm] = av.w;
        sB[lq * 4 + 0][lm] = bv.x; sB[lq * 4 + 1][lm] = bv.y;
        sB[lq * 4 + 2][lm] = bv.z; sB[lq * 4 + 3][lm] = bv.w;
        __syncthreads();
#pragma unroll
        for (int kk = 0; kk < BK; kk++) {
            float4 a4 = *reinterpret_cast<const float4*>(&sA[kk][ty * 4]);
            float4 b4 = *reinterpret_cast<const float4*>(&sB[kk][tx * 4]);
            float a[4] = {a4.x, a4.y, a4.z, a4.w};
            float b[4] = {b4.x, b4.y, b4.z, b4.w};
#pragma unroll
            for (int i = 0; i < 4; i++)
#pragma unroll
                for (int j = 0; j < 4; j++) acc[i][j] += a[i] * b[j];
        }
        __syncthreads();
    }
#pragma unroll
    for (int i = 0; i < 4; i++) {
        int row = t0 + ty * 4 + i;
#pragma unroll
        for (int j = 0; j < 4; j++) {
            int col = n0 + tx * 4 + j;
            g_xg[((size_t)dir * T_LEN + row) * NGATE + col] = acc[i][j] + b1[col] + b2[col];
        }
    }
}

// ---------------- phase 2: recurrence v7 --------------------------------------------------
// R9 compute engine unchanged. Sync replaced: per-CTA double-buffered mbarriers, count=8
// (ONE arrive per source CTA, sent by threads tid<8 after __syncthreads), canonical macro
// forms, explicit cluster-scope fences around the handshake. Overwrite-safety: my store to
// peer buf b^1 happens after wait(full[b]), which required every CTA's arrive, which is
// ordered after that CTA's reads of buf b^1 (its previous dot) via its __syncthreads.
// Phase runahead bounded to 1 by the same dependence chain. Parity at step s: ((s-1)>>1)&1.
__global__ __launch_bounds__(256, 1) __cluster_dims__(8, 1, 1)
void k_rec(const float* __restrict__ WhhF, const float* __restrict__ WhhB,
           const float* __restrict__ h0,   const float* __restrict__ c0) {
    __shared__ __align__(16) float h_sh[2][HDIM];
    __shared__ __align__(8) unsigned long long mbar[2];

    const int rank = (int)cluster_rank();
    const int dir  = (int)(blockIdx.x >> 3);
    const int tid  = threadIdx.x;
    const int unit_local = tid >> 3;              // 0..31
    const int chunk      = tid & 7;               // 0..7
    const int unit       = rank * 32 + unit_local;

    const float* __restrict__ Whh = dir ? WhhB : WhhF;

    // ---- register-resident weights: 4 gates x 8 interleaved float4s (as f32x2 pairs) ----
    unsigned long long w[4][16];
#pragma unroll
    for (int g = 0; g < 4; g++) {
        const float* wrow = Whh + ((size_t)g * HDIM + unit) * HDIM;
#pragma unroll
        for (int j = 0; j < 8; j++) {
            ulonglong2 v = *reinterpret_cast<const ulonglong2*>(wrow + j * 32 + chunk * 4);
            w[g][2 * j]     = v.x;
            w[g][2 * j + 1] = v.y;
        }
    }

    if (tid == 0) {
        MBAR_INIT(smem_u32(&mbar[0]), 8u);
        MBAR_INIT(smem_u32(&mbar[1]), 8u);
    }
    h_sh[0][tid] = h0[dir * HDIM + tid];
    h_sh[1][tid] = 0.0f;
    float c = c0[dir * HDIM + unit];              // replicated across the 8 lanes of a group
    __syncthreads();
    cluster_sync_();   // all CTAs' mbars + h_sh init done before any remote traffic

    // each lane pushes its group's h to CTA == its chunk (one remote store per lane);
    // threads tid<8 own the arrive to rank tid.
    const uint32_t h_rem = mapa_u32(smem_u32(&h_sh[0][0]), chunk);
    uint32_t arr_rem = 0;
    if (tid < 8) arr_rem = mapa_u32(smem_u32(&mbar[0]), tid);
    const uint32_t mb_loc = smem_u32(&mbar[0]);

    // xg pointer + initial prefetch (all lanes of a group load same addrs -> broadcast)
    const float* __restrict__ xgp = g_xg + (size_t)dir * T_LEN * NGATE + unit;
    float xgc[4];
    {
        const int t0 = dir ? (T_LEN - 1) : 0;
#pragma unroll
        for (int g = 0; g < 4; g++) xgc[g] = __ldg(xgp + (size_t)t0 * NGATE + g * HDIM);
    }

    float* __restrict__ hs_out = g_hs + (size_t)dir * T_LEN * HDIM + unit;

    for (int s = 0; s < T_LEN; s++) {
        const int t = dir ? (T_LEN - 1 - s) : s;
        const int b = s & 1;

        if (s) {
            MBAR_WAIT_PARITY(mb_loc + (uint32_t)b * 8u, (uint32_t)(((s - 1) >> 1) & 1));
            asm volatile("fence.acquire.cluster;" ::: "memory");   // see peers' h stores
        }

        // ---- dot: 4 gate rows over interleaved 32-elem subset, h loads reused 4x ----
        const float* hb = &h_sh[b][chunk * 4];
        unsigned long long acc[4] = {0ull, 0ull, 0ull, 0ull};
#pragma unroll
        for (int j = 0; j < 8; j++) {
            ulonglong2 hv = *reinterpret_cast<const ulonglong2*>(hb + j * 32);
#pragma unroll
            for (int g = 0; g < 4; g++) {
                FMA2(acc[g], w[g][2 * j],     hv.x);
                FMA2(acc[g], w[g][2 * j + 1], hv.y);
            }
        }

        float gs[4];
#pragma unroll
        for (int g = 0; g < 4; g++) {
            float lo, hi;
            asm("mov.b64 {%0,%1}, %2;" : "=f"(lo), "=f"(hi) : "l"(acc[g]));
            gs[g] = lo + hi;
        }
        // butterfly over chunk bits: all 8 lanes of a group get bit-identical sums
#pragma unroll
        for (int m = 1; m < 8; m <<= 1) {
#pragma unroll
            for (int g = 0; g < 4; g++)
                gs[g] += __shfl_xor_sync(0xffffffffu, gs[g], m);
        }

        // ---- activation: redundant in all 8 lanes (identical arithmetic) ----
        float gi = gs[0] + xgc[0];
        float gf = gs[1] + xgc[1];
        float gg = gs[2] + xgc[2];
        float go = gs[3] + xgc[3];
        float ii = sigf(gi), ff = sigf(gf), tg = tanh_f(gg), oo = sigf(go);
        c = ff * c + ii * tg;
        float h = oo * tanh_f(c);

        if (s + 1 < T_LEN) {
            // ONE instruction: each lane stores h into buf b^1 of CTA 'chunk'
            const uint32_t off = (uint32_t)(((b ^ 1) * HDIM + unit) * 4);
            asm volatile("st.shared::cluster.f32 [%0], %1;"
                         :: "r"(h_rem + off), "f"(h) : "memory");
        }
        __syncthreads();   // all 256 data stores ordered before the arrives below
        if (s + 1 < T_LEN && tid < 8) {
            asm volatile("fence.release.cluster;" ::: "memory");   // publish data stores
            MBAR_ARRIVE_REMOTE(arr_rem + (uint32_t)(b ^ 1) * 8u);
        }

        // off the critical path: persist h, prefetch next xg
        if (chunk == 0) hs_out[(size_t)t * HDIM] = h;
        if (s + 1 < T_LEN) {
            const int tn = dir ? (T_LEN - 2 - s) : (s + 1);
#pragma unroll
            for (int g = 0; g < 4; g++) xgc[g] = __ldg(xgp + (size_t)tn * NGATE + g * HDIM);
        }
    }
    cluster_sync_();       // drain: no CTA exits while peer traffic could be in flight
    if (tid == 0) {
        asm volatile("mbarrier.inval.shared.b64 [%0];" :: "r"(mb_loc) : "memory");
        asm volatile("mbarrier.inval.shared.b64 [%0];" :: "r"(mb_loc + 8u) : "memory");
    }
}

// ---------------- phase 3: feats[t,k] = [hf(t);hb(t)] . W_out[k] + b_out[k] ----------------
__global__ __launch_bounds__(256) void k_feats(const float* __restrict__ Wout,
                                               const float* __restrict__ bout) {
    const int k  = threadIdx.x & 31;
    const int tl = threadIdx.x >> 5;
    const int t  = blockIdx.x * 8 + tl;
    const float4* hf = reinterpret_cast<const float4*>(g_hs + (size_t)t * HDIM);
    const float4* hb = reinterpret_cast<const float4*>(g_hs + (size_t)T_LEN * HDIM + (size_t)t * HDIM);
    const float4* wr = reinterpret_cast<const float4*>(Wout + (size_t)k * 512);
    float acc = bout[k];
#pragma unroll 8
    for (int d = 0; d < 64; d++) {
        float4 h4 = hf[d]; float4 w4 = wr[d];
        acc += h4.x * w4.x + h4.y * w4.y + h4.z * w4.z + h4.w * w4.w;
    }
#pragma unroll 8
    for (int d = 0; d < 64; d++) {
        float4 h4 = hb[d]; float4 w4 = wr[64 + d];
        acc += h4.x * w4.x + h4.y * w4.y + h4.z * w4.z + h4.w * w4.w;
    }
    g_feats[(size_t)t * TAGS + k] = acc;
}

// ---------------- phase 4: Viterbi v2 — tree-max (1 warp; bps in dyn smem) ----------------
__global__ void k_viterbi(const float* __restrict__ trans, float* __restrict__ out,
                          int out_size) {
    extern __shared__ unsigned char bps[];
    const int lane = threadIdx.x;

    float tr[TAGS];
#pragma unroll
    for (int p = 0; p < TAGS; p++) tr[p] = trans[lane * TAGS + p];
    const float trs = trans[STOPT * TAGS + lane];

    float fv = (lane == STARTT) ? 0.0f : NEGV;
    float fnext = g_feats[lane];
    for (int t = 0; t < T_LEN; t++) {
        const float feat = fnext;
        if (t + 1 < T_LEN) fnext = g_feats[(size_t)(t + 1) * TAGS + lane];

        float sc[TAGS];
#pragma unroll
        for (int p = 0; p < TAGS; p++)
            sc[p] = __shfl_sync(0xffffffffu, fv, p) + tr[p];

        float mv[16]; int mi[16];
#pragma unroll
        for (int i = 0; i < 16; i++) {
            bool take = sc[i + 16] > sc[i];
            mv[i] = take ? sc[i + 16] : sc[i];
            mi[i] = take ? (i + 16) : i;
        }
#pragma unroll
        for (int half = 8; half >= 1; half >>= 1) {
#pragma unroll
            for (int i = 0; i < half; i++) {
                bool take = mv[i + half] > mv[i];
                mv[i] = take ? mv[i + half] : mv[i];
                mi[i] = take ? mi[i + half] : mi[i];
            }
        }
        fv = mv[0] + feat;
        bps[(size_t)t * TAGS + lane] = (unsigned char)mi[0];
    }
    __syncwarp();

    float bv = fv + trs; int bidx = lane;
#pragma unroll
    for (int off = 16; off; off >>= 1) {
        float ov = __shfl_down_sync(0xffffffffu, bv, off);
        int   oi = __shfl_down_sync(0xffffffffu, bidx, off);
        if (ov > bv || (ov == bv && oi < bidx)) { bv = ov; bidx = oi; }
    }
    if (lane == 0) {
        const int off = (out_size > T_LEN) ? 1 : 0;
        if (off) out[0] = bv;
        int b = bidx;
        out[off + T_LEN - 1] = (float)b;
        for (int t = T_LEN - 1; t >= 1; --t) {
            b = (int)bps[(size_t)t * TAGS + b];
            out[off + t - 1] = (float)b;
        }
    }
}

// ---------------- launch ----------------
extern "C" void kernel_launch(void* const* d_in, const int* in_sizes, int n_in,
                              void* d_out, int out_size) {
    (void)in_sizes; (void)n_in;
    const int*   seq   = (const int*)  d_in[0];
    const float* E     = (const float*)d_in[1];
    const float* WihF  = (const float*)d_in[2];
    const float* WhhF  = (const float*)d_in[3];
    const float* bihF  = (const float*)d_in[4];
    const float* bhhF  = (const float*)d_in[5];
    const float* WihB  = (const float*)d_in[6];
    const float* WhhB  = (const float*)d_in[7];
    const float* bihB  = (const float*)d_in[8];
    const float* bhhB  = (const float*)d_in[9];
    const float* h0    = (const float*)d_in[10];
    const float* c0    = (const float*)d_in[11];
    const float* Wout  = (const float*)d_in[12];
    const float* bout  = (const float*)d_in[13];
    const float* trans = (const float*)d_in[14];
    float* out = (float*)d_out;

    k_embed<<<T_LEN, 256>>>(seq, E);
    dim3 gg(NGATE / 64, T_LEN / 64, 2);
    k_xg<<<gg, 256>>>(WihF, WihB, bihF, bhhF, bihB, bhhB);
    k_rec<<<16, 256>>>(WhhF, WhhB, h0, c0);
    k_feats<<<T_LEN / 8, 256>>>(Wout, bout);
    cudaFuncSetAttribute(k_viterbi, cudaFuncAttributeMaxDynamicSharedMemorySize,
                         T_LEN * TAGS);
    k_viterbi<<<1, 32, T_LEN * TAGS>>>(trans, out, out_size);
}